// round 11
// baseline (speedup 1.0000x reference)
#include <cuda_runtime.h>
#include <cuda_bf16.h>
#include <cstdint>

#define N_STREAMS 4
#define C_DIM 4096
#define ROW_ELEMS 16384          // 4 * 4096 floats
#define ROW_BYTES 65536
#define THREADS 512
#define EPS_F 1e-6f
// 8 chunks of 16B per thread: chunk i = n*2+s  (stream n, segment s)
// smem layout: chunk-plane major, lane minor -> conflict-free LDS.128
#define SLOT_BYTES(i, t) ((i) * (THREADS * 16) + (t) * 16)

// "memory" clobber is load-bearing: it pins the program order
//   LDS (current row) -> LDGSTS (next-row prefetch into the SAME slots)
// in compiler output, which the single-buffer WAR safety argument needs.
__device__ __forceinline__ void cp_async16(uint32_t saddr, const void* gptr) {
    asm volatile("cp.async.cg.shared.global [%0], [%1], 16;"
                 :: "r"(saddr), "l"(gptr) : "memory");
}
__device__ __forceinline__ void cp_commit() { asm volatile("cp.async.commit_group;" ::: "memory"); }
__device__ __forceinline__ void cp_wait0()  { asm volatile("cp.async.wait_group 0;" ::: "memory"); }

__global__ __launch_bounds__(THREADS, 2)
void mhc_fused_kernel(const float* __restrict__ x,
                      const float* __restrict__ w,
                      const float* __restrict__ Hpre,
                      const float* __restrict__ Hpost,
                      const float* __restrict__ Hres,
                      float* __restrict__ out,
                      int B)
{
    extern __shared__ char dynbuf[];            // 64KB: next-row staging
    __shared__ __align__(16) float sRed[2][16];
    __shared__ float sM[16];
    __shared__ float sPre[4];
    __shared__ float sPost[4];

    const int t = threadIdx.x;
    const int warp = t >> 5;
    const int lane = t & 31;

    // ---- once per CTA: sigmoids + Sinkhorn on the 4x4 ----
    if (t == 0) {
        float P[16];
#pragma unroll
        for (int i = 0; i < 16; ++i) P[i] = expf(Hres[i]);
#pragma unroll
        for (int it = 0; it < 3; ++it) {
#pragma unroll
            for (int r = 0; r < 4; ++r) {
                float s = P[r*4+0] + P[r*4+1] + P[r*4+2] + P[r*4+3] + EPS_F;
                float inv = 1.0f / s;
#pragma unroll
                for (int cc = 0; cc < 4; ++cc) P[r*4+cc] *= inv;
            }
#pragma unroll
            for (int cc = 0; cc < 4; ++cc) {
                float s = P[0*4+cc] + P[1*4+cc] + P[2*4+cc] + P[3*4+cc] + EPS_F;
                float inv = 1.0f / s;
#pragma unroll
                for (int r = 0; r < 4; ++r) P[r*4+cc] *= inv;
            }
        }
#pragma unroll
        for (int i = 0; i < 16; ++i) sM[i] = P[i];
#pragma unroll
        for (int n = 0; n < 4; ++n) {
            sPre[n]  = 1.0f / (1.0f + expf(-Hpre[n]));
            sPost[n] = 2.0f / (1.0f + expf(-Hpost[n]));
        }
    }
    __syncthreads();

    // per-thread smem slot addresses (own-slot: written and read by this thread only)
    uint32_t saddr[8];
#pragma unroll
    for (int i = 0; i < 8; ++i)
        saddr[i] = (uint32_t)__cvta_generic_to_shared(dynbuf + SLOT_BYTES(i, t));

    // global float4 index within a row for chunk (n, s): n*1024 + s*512 + t
    const float4* xf4 = reinterpret_cast<const float4*>(x);
    float4*       of4 = reinterpret_cast<float4*>(out);
    const float4* wf4 = reinterpret_cast<const float4*>(w);

    // ---- prologue: prefetch first row ----
    {
        size_t rb = (size_t)blockIdx.x * (ROW_ELEMS / 4);
#pragma unroll
        for (int n = 0; n < 4; ++n) {
#pragma unroll
            for (int s = 0; s < 2; ++s)
                cp_async16(saddr[n*2+s], xf4 + rb + n*1024 + s*512 + t);
        }
        cp_commit();
    }

    int k = 0;
    for (int b = blockIdx.x; b < B; b += gridDim.x, ++k) {
        // ---- current row from smem (prefetched) ----
        cp_wait0();
        float4 v[8];
#pragma unroll
        for (int i = 0; i < 8; ++i)
            v[i] = *reinterpret_cast<const float4*>(dynbuf + SLOT_BYTES(i, t));

        // ---- issue prefetch for next row (overlaps all compute below) ----
        // Single-buffer WAR safety: program order LDS->LDGSTS is pinned by the
        // memory clobbers above; the async smem write can only land after its
        // global fetch returns (>=230cyc L2 / ~600cyc DRAM) while the LDS
        // drains in the ~29cyc smem pipeline.
        const int nb = b + gridDim.x;
        if (nb < B) {
            size_t rb = (size_t)nb * (ROW_ELEMS / 4);
#pragma unroll
            for (int n = 0; n < 4; ++n) {
#pragma unroll
                for (int s = 0; s < 2; ++s)
                    cp_async16(saddr[n*2+s], xf4 + rb + n*1024 + s*512 + t);
            }
        }
        cp_commit();

        // unpack: xv[n][j], j = s*4 + c
        float xv[4][8];
#pragma unroll
        for (int n = 0; n < 4; ++n) {
#pragma unroll
            for (int s = 0; s < 2; ++s) {
                float4 q = v[n*2+s];
                xv[n][s*4+0] = q.x; xv[n][s*4+1] = q.y;
                xv[n][s*4+2] = q.z; xv[n][s*4+3] = q.w;
            }
        }

        // weighted aggregation over streams
        float agg[8];
#pragma unroll
        for (int j = 0; j < 8; ++j) {
            float a = sPre[0] * xv[0][j];
            a = fmaf(sPre[1], xv[1][j], a);
            a = fmaf(sPre[2], xv[2][j], a);
            a = fmaf(sPre[3], xv[3][j], a);
            agg[j] = a;
        }

        // sum-of-squares; single barrier + redundant final sum
        float ss = 0.0f;
#pragma unroll
        for (int j = 0; j < 8; ++j) ss = fmaf(agg[j], agg[j], ss);
#pragma unroll
        for (int off = 16; off > 0; off >>= 1)
            ss += __shfl_xor_sync(0xFFFFFFFFu, ss, off);
        const int p = k & 1;
        if (lane == 0) sRed[p][warp] = ss;
        __syncthreads();
        float total;
        {
            const float4* r4 = reinterpret_cast<const float4*>(sRed[p]);
            float4 a0 = r4[0], a1 = r4[1], a2 = r4[2], a3 = r4[3];
            total = ((a0.x + a0.y) + (a0.z + a0.w))
                  + ((a1.x + a1.y) + (a1.z + a1.w))
                  + ((a2.x + a2.y) + (a2.z + a2.w))
                  + ((a3.x + a3.y) + (a3.z + a3.w));
        }
        const float invRms = 1.0f / sqrtf(total * (1.0f / (float)C_DIM) + EPS_F);

        // y_norm with exact bf16 round-trip (w is L1-resident; two contiguous float4)
        {
            float4 wA = wf4[t];
            float4 wB = wf4[512 + t];
            float wv[8] = {wA.x, wA.y, wA.z, wA.w, wB.x, wB.y, wB.z, wB.w};
#pragma unroll
            for (int j = 0; j < 8; ++j) {
                float y = agg[j] * invRms * wv[j];
                agg[j] = __bfloat162float(__float2bfloat16(y));
            }
        }

        // mix + scaled-norm add, streaming stores (evict-first: output never re-read)
        const size_t ob = (size_t)b * (ROW_ELEMS / 4);
#pragma unroll
        for (int n = 0; n < 4; ++n) {
            const float m0 = sM[n*4+0], m1 = sM[n*4+1], m2 = sM[n*4+2], m3 = sM[n*4+3];
            const float hp = sPost[n];
            float o[8];
#pragma unroll
            for (int j = 0; j < 8; ++j) {
                float vv = m0 * xv[0][j];
                vv = fmaf(m1, xv[1][j], vv);
                vv = fmaf(m2, xv[2][j], vv);
                vv = fmaf(m3, xv[3][j], vv);
                o[j] = fmaf(hp, agg[j], vv);
            }
            __stcs(&of4[ob + n*1024 + 0*512 + t], make_float4(o[0], o[1], o[2], o[3]));
            __stcs(&of4[ob + n*1024 + 1*512 + t], make_float4(o[4], o[5], o[6], o[7]));
        }
    }
}

extern "C" void kernel_launch(void* const* d_in, const int* in_sizes, int n_in,
                              void* d_out, int out_size)
{
    const float* x     = (const float*)d_in[0];
    const float* w     = (const float*)d_in[1];
    const float* Hpre  = (const float*)d_in[2];
    const float* Hpost = (const float*)d_in[3];
    const float* Hres  = (const float*)d_in[4];
    float* out = (float*)d_out;

    const int B = in_sizes[0] / ROW_ELEMS;

    int sm_count = 0;
    cudaDeviceGetAttribute(&sm_count, cudaDevAttrMultiProcessorCount, 0);
    if (sm_count <= 0) sm_count = 148;
    int grid = sm_count * 2;            // occ=2 persistent CTAs
    if (grid > B) grid = B;

    // 64KB dynamic smem staging buffer (attribute set is immediate, not captured)
    cudaFuncSetAttribute(mhc_fused_kernel,
                         cudaFuncAttributeMaxDynamicSharedMemorySize, ROW_BYTES);

    mhc_fused_kernel<<<grid, THREADS, ROW_BYTES>>>(x, w, Hpre, Hpost, Hres, out, B);
}